// round 2
// baseline (speedup 1.0000x reference)
#include <cuda_runtime.h>

#define HIDN 50
#define KB 10
#define TDN 8
#define BBOUND 3.0f
#define TPB 256
#define PAD 52
#define MAXBLK 8192

// smem offsets (floats), all 16B-aligned
#define OFF_W0T 0                 // 50*8   = 400
#define OFF_B0  400               // pad to 52
#define OFF_W1T 452               // 50*52  = 2600
#define OFF_B1  3052              // pad to 52
#define OFF_WWT 3104              // 80*52  = 4160
#define OFF_BW  7264              // 80
#define OFF_WHT 7344              // 80*52  = 4160
#define OFF_BH  11504             // 80
#define OFF_WDT 11584             // 72*52  = 3744
#define OFF_BD  15328             // 72
#define SMEM_FLOATS 15400
#define SMEM_BYTES (SMEM_FLOATS * 4)

__device__ float g_partial[MAXBLK];

// ---- packed f32x2 helpers (sm_103a FFMA2 path) ----
__device__ __forceinline__ unsigned long long pk2(float lo, float hi) {
    unsigned long long r;
    asm("mov.b64 %0, {%1, %2};" : "=l"(r) : "f"(lo), "f"(hi));
    return r;
}
__device__ __forceinline__ void upk2(unsigned long long v, float& lo, float& hi) {
    asm("mov.b64 {%0, %1}, %2;" : "=f"(lo), "=f"(hi) : "l"(v));
}
__device__ __forceinline__ unsigned long long fma2(unsigned long long a,
                                                   unsigned long long b,
                                                   unsigned long long c) {
    unsigned long long d;
    asm("fma.rn.f32x2 %0, %1, %2, %3;" : "=l"(d) : "l"(a), "l"(b), "l"(c));
    return d;
}
__device__ __forceinline__ unsigned long long add2(unsigned long long a,
                                                   unsigned long long b) {
    unsigned long long d;
    asm("add.rn.f32x2 %0, %1, %2;" : "=l"(d) : "l"(a), "l"(b));
    return d;
}

__device__ __forceinline__ float ftanh(float v) {
    float e = __expf(2.0f * v);
    return 1.0f - __fdividef(2.0f, e + 1.0f);
}

__device__ __forceinline__ float fsoftplus(float v) {
    return fmaxf(v, 0.0f) + log1pf(__expf(-fabsf(v)));
}

// dot of 52 floats: operand pairs packed in gp[26], weights contiguous in smem
__device__ __forceinline__ float dot52p(const unsigned long long* __restrict__ gp,
                                        const float* __restrict__ w) {
    unsigned long long a0 = 0ULL, a1 = 0ULL;
#pragma unroll
    for (int q = 0; q < 13; q++) {
        ulonglong2 w2 = reinterpret_cast<const ulonglong2*>(w)[q];
        a0 = fma2(gp[2 * q + 0], w2.x, a0);
        a1 = fma2(gp[2 * q + 1], w2.y, a1);
    }
    unsigned long long s = add2(a0, a1);
    float lo, hi;
    upk2(s, lo, hi);
    return lo + hi;
}

__global__ void __launch_bounds__(TPB) nsf_kernel(
    const float* __restrict__ x,
    const float* __restrict__ w0, const float* __restrict__ b0,
    const float* __restrict__ w1, const float* __restrict__ b1,
    const float* __restrict__ ww, const float* __restrict__ bw,
    const float* __restrict__ wh, const float* __restrict__ bh,
    const float* __restrict__ wd, const float* __restrict__ bd,
    float* __restrict__ out, int n) {
    extern __shared__ float sm[];
    int tid = threadIdx.x;

    for (int i = tid; i < SMEM_FLOATS; i += TPB) sm[i] = 0.0f;
    __syncthreads();

    for (int i = tid; i < 8 * HIDN; i += TPB) {
        int k = i / HIDN, j = i % HIDN;
        sm[OFF_W0T + j * 8 + k] = w0[i];
    }
    for (int i = tid; i < HIDN; i += TPB) {
        sm[OFF_B0 + i] = b0[i];
        sm[OFF_B1 + i] = b1[i];
    }
    for (int i = tid; i < HIDN * HIDN; i += TPB) {
        int k = i / HIDN, j = i % HIDN;
        sm[OFF_W1T + j * PAD + k] = w1[i];
    }
    for (int i = tid; i < HIDN * 80; i += TPB) {
        int j = i / 80, o = i % 80;
        sm[OFF_WWT + o * PAD + j] = ww[i];
        sm[OFF_WHT + o * PAD + j] = wh[i];
    }
    for (int i = tid; i < 80; i += TPB) {
        sm[OFF_BW + i] = bw[i];
        sm[OFF_BH + i] = bh[i];
    }
    for (int i = tid; i < HIDN * 72; i += TPB) {
        int j = i / 72, o = i % 72;
        sm[OFF_WDT + o * PAD + j] = wd[i];
    }
    for (int i = tid; i < 72; i += TPB) sm[OFF_BD + i] = bd[i];
    __syncthreads();

    int row = blockIdx.x * TPB + tid;
    float ld_acc = 0.0f;

    if (row < n) {
        const float4* xr = reinterpret_cast<const float4*>(x + (size_t)row * 16);
        float4 x0 = xr[0], x1 = xr[1], x2 = xr[2], x3 = xr[3];
        unsigned long long zdp[4] = {pk2(x0.x, x0.y), pk2(x0.z, x0.w),
                                     pk2(x1.x, x1.y), pk2(x1.z, x1.w)};
        float uarr[8] = {x2.x, x2.y, x2.z, x2.w, x3.x, x3.y, x3.z, x3.w};

        // layer 0: 8 -> 50, tanh; pack activation pairs
        unsigned long long hp[26];
#pragma unroll
        for (int jp = 0; jp < 25; jp++) {
            float t01[2];
#pragma unroll
            for (int s = 0; s < 2; s++) {
                int j = 2 * jp + s;
                const ulonglong2* wv =
                    reinterpret_cast<const ulonglong2*>(&sm[OFF_W0T + j * 8]);
                ulonglong2 wq = wv[0];
                unsigned long long a0 = fma2(zdp[0], wq.x, 0ULL);
                unsigned long long a1 = fma2(zdp[1], wq.y, 0ULL);
                ulonglong2 wq2 = wv[1];
                a0 = fma2(zdp[2], wq2.x, a0);
                a1 = fma2(zdp[3], wq2.y, a1);
                float lo, hi;
                upk2(add2(a0, a1), lo, hi);
                t01[s] = ftanh(lo + hi + sm[OFF_B0 + j]);
            }
            hp[jp] = pk2(t01[0], t01[1]);
        }
        hp[25] = 0ULL;

        // layer 1: 50 -> 50, tanh; pack pairs
        unsigned long long gp[26];
#pragma unroll
        for (int jp = 0; jp < 25; jp++) {
            float t0 = ftanh(dot52p(hp, &sm[OFF_W1T + (2 * jp + 0) * PAD]) +
                             sm[OFF_B1 + 2 * jp + 0]);
            float t1 = ftanh(dot52p(hp, &sm[OFF_W1T + (2 * jp + 1) * PAD]) +
                             sm[OFF_B1 + 2 * jp + 1]);
            gp[jp] = pk2(t0, t1);
        }
        gp[25] = 0ULL;

        float zout[8];
#pragma unroll 1
        for (int dd = 0; dd < TDN; dd++) {
            float lw[KB], lh[KB], dv[KB + 1];
#pragma unroll
            for (int kk = 0; kk < KB; kk++) {
                int o = dd * KB + kk;
                lw[kk] = 6.0f * (dot52p(gp, &sm[OFF_WWT + o * PAD]) + sm[OFF_BW + o]);
                lh[kk] = 6.0f * (dot52p(gp, &sm[OFF_WHT + o * PAD]) + sm[OFF_BH + o]);
            }
            dv[0] = 1.0f;
            dv[KB] = 1.0f;
#pragma unroll
            for (int kk = 0; kk < KB - 1; kk++) {
                int o = dd * (KB - 1) + kk;
                dv[kk + 1] =
                    fsoftplus(dot52p(gp, &sm[OFF_WDT + o * PAD]) + sm[OFF_BD + o]);
            }

            float mw = lw[0], mh = lh[0];
#pragma unroll
            for (int kk = 1; kk < KB; kk++) {
                mw = fmaxf(mw, lw[kk]);
                mh = fmaxf(mh, lh[kk]);
            }
            float sw = 0.f, sh = 0.f;
#pragma unroll
            for (int kk = 0; kk < KB; kk++) {
                lw[kk] = __expf(lw[kk] - mw); sw += lw[kk];
                lh[kk] = __expf(lh[kk] - mh); sh += lh[kk];
            }
            float iw = __fdividef(6.0f, sw);
            float ih = __fdividef(6.0f, sh);

            float uu = uarr[dd];
            bool inside = (uu > -BBOUND) && (uu < BBOUND);
            float uc = fminf(fmaxf(uu, -BBOUND), BBOUND);

            float xcur = -BBOUND, ycur = -BBOUND;
            float xk = -BBOUND, yk = -BBOUND, wk = 1.0f, hk = 1.0f;
            float dk = 1.0f, dk1 = 1.0f;
#pragma unroll
            for (int kk = 0; kk < KB; kk++) {
                float wkk = lw[kk] * iw;
                float hkk = lh[kk] * ih;
                if (uc >= xcur) {
                    xk = xcur; yk = ycur; wk = wkk; hk = hkk;
                    dk = dv[kk]; dk1 = dv[kk + 1];
                }
                xcur += wkk;
                ycur += hkk;
            }

            float sk = __fdividef(hk, wk);
            float xi = __fdividef(uc - xk, wk);
            float om = 1.0f - xi;
            float xiom = xi * om;
            float denom = sk + (dk1 + dk - 2.0f * sk) * xiom;
            float y = yk + hk * __fdividef(sk * xi * xi + dk * xiom, denom);
            // 2log(sk)+log(num)-2log(denom) = log(sk^2*num/denom^2)
            float num = dk1 * xi * xi + 2.0f * sk * xiom + dk * om * om;
            float ldet = __logf(__fdividef(sk * sk * num, denom * denom));
            zout[dd] = inside ? y : uu;
            ld_acc += inside ? ldet : 0.0f;
        }

        float4* orow = reinterpret_cast<float4*>(out + (size_t)row * 16);
        orow[0] = x0;
        orow[1] = x1;
        orow[2] = make_float4(zout[0], zout[1], zout[2], zout[3]);
        orow[3] = make_float4(zout[4], zout[5], zout[6], zout[7]);
    }

    // block reduce logdet -> per-block partial (no atomics, no zero kernel)
#pragma unroll
    for (int off = 16; off > 0; off >>= 1)
        ld_acc += __shfl_down_sync(0xffffffffu, ld_acc, off);
    __shared__ float s_red[TPB / 32];
    if ((tid & 31) == 0) s_red[tid >> 5] = ld_acc;
    __syncthreads();
    if (tid == 0) {
        float t = 0.f;
#pragma unroll
        for (int i = 0; i < TPB / 32; i++) t += s_red[i];
        g_partial[blockIdx.x] = t;
    }
}

__global__ void k_reduce_ld(float* o, int nblocks) {
    int tid = threadIdx.x;
    double acc = 0.0;
    for (int i = tid; i < nblocks; i += TPB) acc += (double)g_partial[i];
#pragma unroll
    for (int off = 16; off > 0; off >>= 1)
        acc += __shfl_down_sync(0xffffffffu, acc, off);
    __shared__ double s_red[TPB / 32];
    if ((tid & 31) == 0) s_red[tid >> 5] = acc;
    __syncthreads();
    if (tid == 0) {
        double t = 0.0;
#pragma unroll
        for (int i = 0; i < TPB / 32; i++) t += s_red[i];
        *o = (float)t;
    }
}

extern "C" void kernel_launch(void* const* d_in, const int* in_sizes, int n_in,
                              void* d_out, int out_size) {
    const float* x  = (const float*)d_in[0];
    const float* w0 = (const float*)d_in[1];
    const float* b0 = (const float*)d_in[2];
    const float* w1 = (const float*)d_in[3];
    const float* b1 = (const float*)d_in[4];
    const float* ww = (const float*)d_in[5];
    const float* bw = (const float*)d_in[6];
    const float* wh = (const float*)d_in[7];
    const float* bh = (const float*)d_in[8];
    const float* wd = (const float*)d_in[9];
    const float* bd = (const float*)d_in[10];
    float* out = (float*)d_out;

    int n = in_sizes[0] / 16;
    int nblocks = (n + TPB - 1) / TPB;
    if (nblocks > MAXBLK) nblocks = MAXBLK;  // n=262144 -> 1024

    cudaFuncSetAttribute(nsf_kernel, cudaFuncAttributeMaxDynamicSharedMemorySize,
                         SMEM_BYTES);

    nsf_kernel<<<(n + TPB - 1) / TPB, TPB, SMEM_BYTES>>>(
        x, w0, b0, w1, b1, ww, bw, wh, bh, wd, bd, out, n);
    if (out_size > n * 16) {
        k_reduce_ld<<<1, TPB>>>(out + n * 16, nblocks);
    }
}

// round 3
// speedup vs baseline: 1.2083x; 1.2083x over previous
#include <cuda_runtime.h>

#define HIDN 50
#define KB 10
#define TDN 8
#define BBOUND 3.0f
#define TPB 256
#define PAD 52
#define MAXBLK 8192

// smem offsets (floats), all 16B-aligned
#define OFF_W0T 0                 // 50*8   = 400
#define OFF_B0  400               // pad to 52
#define OFF_W1T 452               // 50*52  = 2600
#define OFF_B1  3052              // pad to 52
#define OFF_WWT 3104              // 80*52  = 4160 (prescaled by 6)
#define OFF_BW  7264              // 80 (prescaled by 6)
#define OFF_WHT 7344              // 80*52  = 4160 (prescaled by 6)
#define OFF_BH  11504             // 80 (prescaled by 6)
#define OFF_WDT 11584             // 72*52  = 3744
#define OFF_BD  15328             // 72
#define SMEM_FLOATS 15400
#define SMEM_BYTES (SMEM_FLOATS * 4)

__device__ float g_partial[MAXBLK];
__device__ unsigned int g_count = 0;

__device__ __forceinline__ float ftanh(float v) {
    float e = __expf(2.0f * v);
    return 1.0f - __fdividef(2.0f, e + 1.0f);
}

__device__ __forceinline__ float fsoftplus(float v) {
    return fmaxf(v, 0.0f) + log1pf(__expf(-fabsf(v)));
}

// dot of 52 elements (last 2 are zero pads), 4-way ILP, vectorized smem loads
__device__ __forceinline__ float dot52(const float* __restrict__ h,
                                       const float* __restrict__ w) {
    float a0 = 0.f, a1 = 0.f, a2 = 0.f, a3 = 0.f;
#pragma unroll
    for (int q = 0; q < 13; q++) {
        float4 w4 = reinterpret_cast<const float4*>(w)[q];
        a0 = fmaf(h[4 * q + 0], w4.x, a0);
        a1 = fmaf(h[4 * q + 1], w4.y, a1);
        a2 = fmaf(h[4 * q + 2], w4.z, a2);
        a3 = fmaf(h[4 * q + 3], w4.w, a3);
    }
    return (a0 + a1) + (a2 + a3);
}

__global__ void __launch_bounds__(TPB, 2) nsf_kernel(
    const float* __restrict__ x,
    const float* __restrict__ w0, const float* __restrict__ b0,
    const float* __restrict__ w1, const float* __restrict__ b1,
    const float* __restrict__ ww, const float* __restrict__ bw,
    const float* __restrict__ wh, const float* __restrict__ bh,
    const float* __restrict__ wd, const float* __restrict__ bd,
    float* __restrict__ out, int n, int has_ld) {
    extern __shared__ float sm[];
    int tid = threadIdx.x;

    for (int i = tid; i < SMEM_FLOATS; i += TPB) sm[i] = 0.0f;
    __syncthreads();

    for (int i = tid; i < 8 * HIDN; i += TPB) {
        int k = i / HIDN, j = i % HIDN;
        sm[OFF_W0T + j * 8 + k] = w0[i];
    }
    for (int i = tid; i < HIDN; i += TPB) {
        sm[OFF_B0 + i] = b0[i];
        sm[OFF_B1 + i] = b1[i];
    }
    for (int i = tid; i < HIDN * HIDN; i += TPB) {
        int k = i / HIDN, j = i % HIDN;
        sm[OFF_W1T + j * PAD + k] = w1[i];
    }
    // prescale the softmax-head weights by 2B = 6
    for (int i = tid; i < HIDN * 80; i += TPB) {
        int j = i / 80, o = i % 80;
        sm[OFF_WWT + o * PAD + j] = 6.0f * ww[i];
        sm[OFF_WHT + o * PAD + j] = 6.0f * wh[i];
    }
    for (int i = tid; i < 80; i += TPB) {
        sm[OFF_BW + i] = 6.0f * bw[i];
        sm[OFF_BH + i] = 6.0f * bh[i];
    }
    for (int i = tid; i < HIDN * 72; i += TPB) {
        int j = i / 72, o = i % 72;
        sm[OFF_WDT + o * PAD + j] = wd[i];
    }
    for (int i = tid; i < 72; i += TPB) sm[OFF_BD + i] = bd[i];
    __syncthreads();

    int row = blockIdx.x * TPB + tid;
    float ld_acc = 0.0f;

    if (row < n) {
        const float* xrow = x + (size_t)row * 16;
        float* orow = out + (size_t)row * 16;
        const float4* xr = reinterpret_cast<const float4*>(xrow);
        float4 x0 = xr[0], x1 = xr[1];
        // passthrough columns written immediately (frees the regs)
        float4* ov = reinterpret_cast<float4*>(orow);
        ov[0] = x0;
        ov[1] = x1;
        float zd[8] = {x0.x, x0.y, x0.z, x0.w, x1.x, x1.y, x1.z, x1.w};

        // layer 0: 8 -> 50, tanh
        float h[PAD];
#pragma unroll
        for (int j = 0; j < HIDN; j++) {
            const float4* wv = reinterpret_cast<const float4*>(&sm[OFF_W0T + j * 8]);
            float4 a = wv[0], b = wv[1];
            float acc = sm[OFF_B0 + j];
            acc = fmaf(zd[0], a.x, acc);
            acc = fmaf(zd[1], a.y, acc);
            acc = fmaf(zd[2], a.z, acc);
            acc = fmaf(zd[3], a.w, acc);
            acc = fmaf(zd[4], b.x, acc);
            acc = fmaf(zd[5], b.y, acc);
            acc = fmaf(zd[6], b.z, acc);
            acc = fmaf(zd[7], b.w, acc);
            h[j] = ftanh(acc);
        }
        h[50] = 0.f; h[51] = 0.f;

        // layer 1: 50 -> 50, tanh
        float g[PAD];
#pragma unroll
        for (int j = 0; j < HIDN; j++) {
            g[j] = ftanh(dot52(h, &sm[OFF_W1T + j * PAD]) + sm[OFF_B1 + j]);
        }
        g[50] = 0.f; g[51] = 0.f;

        float zo0 = 0.f;
#pragma unroll 1
        for (int dd = 0; dd < TDN; dd++) {
            float lw[KB], lh[KB], dv[KB + 1];
#pragma unroll
            for (int kk = 0; kk < KB; kk++) {
                int o = dd * KB + kk;
                lw[kk] = dot52(g, &sm[OFF_WWT + o * PAD]) + sm[OFF_BW + o];
                lh[kk] = dot52(g, &sm[OFF_WHT + o * PAD]) + sm[OFF_BH + o];
            }
            dv[0] = 1.0f;
            dv[KB] = 1.0f;
#pragma unroll
            for (int kk = 0; kk < KB - 1; kk++) {
                int o = dd * (KB - 1) + kk;
                dv[kk + 1] =
                    fsoftplus(dot52(g, &sm[OFF_WDT + o * PAD]) + sm[OFF_BD + o]);
            }

            float mw = lw[0], mh = lh[0];
#pragma unroll
            for (int kk = 1; kk < KB; kk++) {
                mw = fmaxf(mw, lw[kk]);
                mh = fmaxf(mh, lh[kk]);
            }
            float sw = 0.f, sh = 0.f;
#pragma unroll
            for (int kk = 0; kk < KB; kk++) {
                lw[kk] = __expf(lw[kk] - mw); sw += lw[kk];
                lh[kk] = __expf(lh[kk] - mh); sh += lh[kk];
            }

            float uu = xrow[8 + dd];
            bool inside = (uu > -BBOUND) && (uu < BBOUND);
            float uc = fminf(fmaxf(uu, -BBOUND), BBOUND);

            // raw-cumsum bin select: uc >= xe_k  <=>  cumsum_w[k] <= tw
            float tw = (uc + BBOUND) * sw * (1.0f / 6.0f);
            float cw = 0.f, cy = 0.f;
            float csel = 0.f, cysel = 0.f;
            float wsel = lw[0], hsel = lh[0];
            float dk = dv[0], dk1 = dv[1];
#pragma unroll
            for (int kk = 1; kk < KB; kk++) {
                cw += lw[kk - 1];
                cy += lh[kk - 1];
                if (cw <= tw) {
                    csel = cw; cysel = cy;
                    wsel = lw[kk]; hsel = lh[kk];
                    dk = dv[kk]; dk1 = dv[kk + 1];
                }
            }

            float inv_sh = __fdividef(1.0f, sh);
            float inv_w = __fdividef(1.0f, wsel);
            float xi = (tw - csel) * inv_w;         // == (uc - xk)/wk
            float hk = 6.0f * hsel * inv_sh;
            float yk = fmaf(6.0f * cysel, inv_sh, -BBOUND);
            float sk = hsel * sw * inv_sh * inv_w;  // hk/wk
            float om = 1.0f - xi;
            float xiom = xi * om;
            float denom = sk + (dk1 + dk - 2.0f * sk) * xiom;
            float y = yk + hk * __fdividef(sk * xi * xi + dk * xiom, denom);
            float num = dk1 * xi * xi + 2.0f * sk * xiom + dk * om * om;
            float ldet = __logf(__fdividef(sk * sk * num, denom * denom));

            float zv = inside ? y : uu;
            ld_acc += inside ? ldet : 0.0f;
            if (dd & 1) {
                reinterpret_cast<float2*>(orow)[4 + (dd >> 1)] =
                    make_float2(zo0, zv);
            } else {
                zo0 = zv;
            }
        }
    }

    // block reduce logdet -> per-block partial
#pragma unroll
    for (int off = 16; off > 0; off >>= 1)
        ld_acc += __shfl_down_sync(0xffffffffu, ld_acc, off);
    __shared__ float s_red[TPB / 32];
    __shared__ bool s_last;
    if ((tid & 31) == 0) s_red[tid >> 5] = ld_acc;
    __syncthreads();
    if (tid == 0) {
        float t = 0.f;
#pragma unroll
        for (int i = 0; i < TPB / 32; i++) t += s_red[i];
        g_partial[blockIdx.x] = t;
        __threadfence();
        unsigned int done = atomicAdd(&g_count, 1u);
        s_last = (done == gridDim.x - 1);
    }
    __syncthreads();

    if (s_last) {
        // last block: reduce all partials (deterministic order)
        __threadfence();
        int nb = gridDim.x;
        double acc = 0.0;
        for (int i = tid; i < nb; i += TPB) acc += (double)g_partial[i];
#pragma unroll
        for (int off = 16; off > 0; off >>= 1)
            acc += __shfl_down_sync(0xffffffffu, acc, off);
        __shared__ double s_dred[TPB / 32];
        if ((tid & 31) == 0) s_dred[tid >> 5] = acc;
        __syncthreads();
        if (tid == 0) {
            double t = 0.0;
#pragma unroll
            for (int i = 0; i < TPB / 32; i++) t += s_dred[i];
            if (has_ld) out[(size_t)n * 16] = (float)t;
            g_count = 0;  // reset for next (graph-replayed) call
        }
    }
}

extern "C" void kernel_launch(void* const* d_in, const int* in_sizes, int n_in,
                              void* d_out, int out_size) {
    const float* x  = (const float*)d_in[0];
    const float* w0 = (const float*)d_in[1];
    const float* b0 = (const float*)d_in[2];
    const float* w1 = (const float*)d_in[3];
    const float* b1 = (const float*)d_in[4];
    const float* ww = (const float*)d_in[5];
    const float* bw = (const float*)d_in[6];
    const float* wh = (const float*)d_in[7];
    const float* bh = (const float*)d_in[8];
    const float* wd = (const float*)d_in[9];
    const float* bd = (const float*)d_in[10];
    float* out = (float*)d_out;

    int n = in_sizes[0] / 16;
    int has_ld = (out_size > n * 16) ? 1 : 0;

    cudaFuncSetAttribute(nsf_kernel, cudaFuncAttributeMaxDynamicSharedMemorySize,
                         SMEM_BYTES);

    nsf_kernel<<<(n + TPB - 1) / TPB, TPB, SMEM_BYTES>>>(
        x, w0, b0, w1, b1, ww, bw, wh, bh, wd, bd, out, n, has_ld);
}